// round 14
// baseline (speedup 1.0000x reference)
#include <cuda_runtime.h>
#include <math.h>

#define N_NODES 100000
#define N_EDGES 1600000
#define HID 64

// Weights in constant memory (filled by async D2D copies in kernel_launch).
__constant__ float cW[HID * HID];      // W_in
__constant__ float cB[HID];            // b_in
__constant__ float cWe[2 * HID];       // W_edge (Wu | Wv)
__constant__ float cWo[2 * HID];       // W_out row-major [64][2]

// Scratch (no cudaMalloc allowed).
__device__ float4 g_node[N_NODES];   // (dotu, dotv, z0, z1) per node, 1.6 MB
__device__ float4 g_acc[N_NODES];    // (sum_w*z0, sum_w*z1, deg, pad), 1.6 MB

// ---------------------------------------------------------------------------
// f32x2 helpers (packed dual-fp32 FMA).
// ---------------------------------------------------------------------------
__device__ __forceinline__ unsigned long long pack2(float x, float y) {
    unsigned long long r;
    asm("mov.b64 %0, {%1, %2};" : "=l"(r) : "f"(x), "f"(y));
    return r;
}
__device__ __forceinline__ void unpack2(unsigned long long v, float& x, float& y) {
    asm("mov.b64 {%0, %1}, %2;" : "=f"(x), "=f"(y) : "l"(v));
}
__device__ __forceinline__ void fma2(unsigned long long& acc,
                                     unsigned long long a,
                                     unsigned long long b) {
    asm("fma.rn.f32x2 %0, %1, %2, %0;" : "+l"(acc) : "l"(a), "l"(b));
}

// ---------------------------------------------------------------------------
// K1: h = feat @ W_in + b_in. Weights from CONSTANT memory (warp-uniform ->
// LDCU on the uniform port); feat tile in smem; 2 nodes per thread
// (128 nodes/block). h stays in registers; emits the four per-node linear
// functionals (dotu, dotv, z0, z1) into g_node and zeroes g_acc.
// ---------------------------------------------------------------------------
__global__ void __launch_bounds__(256)
input_gemm_kernel(const float* __restrict__ feat) {
    __shared__ float sT[HID][130];      // transposed feat tile, 128 nodes (+pad)
    __shared__ float sP[4][128][4];     // per-q partials (du,dv,z0,z1)

    int tid   = threadIdx.x;
    int node0 = blockIdx.x * 128;
    int n     = tid & 63;
    int q     = tid >> 6;               // constant within a warp
    int j0    = q * 16;

    // stage transposed feat tile (coalesced global reads)
    for (int idx = tid; idx < 128 * HID; idx += 256) {
        int nn = idx >> 6, k = idx & 63;
        int gn = node0 + nn;
        sT[k][nn] = (gn < N_NODES) ? feat[gn * HID + k] : 0.0f;
    }
    __syncthreads();

    unsigned long long acc0[8], acc1[8];
#pragma unroll
    for (int p = 0; p < 8; p++) {
        unsigned long long b = pack2(cB[j0 + 2 * p], cB[j0 + 2 * p + 1]);
        acc0[p] = b;
        acc1[p] = b;
    }

    const ulonglong2* cW2 = (const ulonglong2*)cW;   // row k = 16 ulonglong2
#pragma unroll 4
    for (int k = 0; k < HID; k++) {
        float f0 = sT[k][n];
        float f1 = sT[k][n + 64];
        unsigned long long ff0 = pack2(f0, f0);
        unsigned long long ff1 = pack2(f1, f1);
        ulonglong2 wA = cW2[k * 16 + q * 4 + 0];
        ulonglong2 wB = cW2[k * 16 + q * 4 + 1];
        ulonglong2 wC = cW2[k * 16 + q * 4 + 2];
        ulonglong2 wD = cW2[k * 16 + q * 4 + 3];
        fma2(acc0[0], ff0, wA.x); fma2(acc0[1], ff0, wA.y);
        fma2(acc0[2], ff0, wB.x); fma2(acc0[3], ff0, wB.y);
        fma2(acc0[4], ff0, wC.x); fma2(acc0[5], ff0, wC.y);
        fma2(acc0[6], ff0, wD.x); fma2(acc0[7], ff0, wD.y);
        fma2(acc1[0], ff1, wA.x); fma2(acc1[1], ff1, wA.y);
        fma2(acc1[2], ff1, wB.x); fma2(acc1[3], ff1, wB.y);
        fma2(acc1[4], ff1, wC.x); fma2(acc1[5], ff1, wC.y);
        fma2(acc1[6], ff1, wD.x); fma2(acc1[7], ff1, wD.y);
    }

    // per-thread partial functionals for both nodes (constant weights)
    float du0 = 0.f, dv0 = 0.f, z00 = 0.f, z10 = 0.f;
    float du1 = 0.f, dv1 = 0.f, z01 = 0.f, z11 = 0.f;
#pragma unroll
    for (int p = 0; p < 8; p++) {
        float x0, y0, x1, y1;
        unpack2(acc0[p], x0, y0);
        unpack2(acc1[p], x1, y1);
        int j = j0 + 2 * p;
        float wu0 = cWe[j],           wu1 = cWe[j + 1];
        float wv0 = cWe[HID + j],     wv1 = cWe[HID + j + 1];
        float wo00 = cWo[2 * j],      wo01 = cWo[2 * j + 2];
        float wo10 = cWo[2 * j + 1],  wo11 = cWo[2 * j + 3];
        du0 = fmaf(x0, wu0, fmaf(y0, wu1, du0));
        dv0 = fmaf(x0, wv0, fmaf(y0, wv1, dv0));
        z00 = fmaf(x0, wo00, fmaf(y0, wo01, z00));
        z10 = fmaf(x0, wo10, fmaf(y0, wo11, z10));
        du1 = fmaf(x1, wu0, fmaf(y1, wu1, du1));
        dv1 = fmaf(x1, wv0, fmaf(y1, wv1, dv1));
        z01 = fmaf(x1, wo00, fmaf(y1, wo01, z01));
        z11 = fmaf(x1, wo10, fmaf(y1, wo11, z11));
    }
    sP[q][n][0]      = du0; sP[q][n][1]      = dv0;
    sP[q][n][2]      = z00; sP[q][n][3]      = z10;
    sP[q][n + 64][0] = du1; sP[q][n + 64][1] = dv1;
    sP[q][n + 64][2] = z01; sP[q][n + 64][3] = z11;
    __syncthreads();

    if (tid < 128) {
        int gn = node0 + tid;
        if (gn < N_NODES) {
            float4 r;
            r.x = sP[0][tid][0] + sP[1][tid][0] + sP[2][tid][0] + sP[3][tid][0];
            r.y = sP[0][tid][1] + sP[1][tid][1] + sP[2][tid][1] + sP[3][tid][1];
            r.z = sP[0][tid][2] + sP[1][tid][2] + sP[2][tid][2] + sP[3][tid][2];
            r.w = sP[0][tid][3] + sP[1][tid][3] + sP[2][tid][3] + sP[3][tid][3];
            g_node[gn] = r;
            g_acc[gn]  = make_float4(0.f, 0.f, 0.f, 0.f);   // fused zeroing
        }
    }
}

// ---------------------------------------------------------------------------
// K2: edge scatter — gate + projected message, ONE vector RED per edge:
//   g_acc[dst] += (w*z0, w*z1, 1, 0).  8 edges per thread (MLP 16).
// ---------------------------------------------------------------------------
__global__ void scatter_kernel(const int* __restrict__ src,
                               const int* __restrict__ dst,
                               const float* __restrict__ b_edge) {
    int t = blockIdx.x * blockDim.x + threadIdx.x;
    if (t * 8 >= N_EDGES) return;
    const int4* s4 = (const int4*)src;
    const int4* d4 = (const int4*)dst;
    int4 sA = s4[2 * t], sB = s4[2 * t + 1];
    int4 dA = d4[2 * t], dB = d4[2 * t + 1];
    float be = b_edge[0];
    const float* nodef = (const float*)g_node;

    float4 a0 = g_node[sA.x], a1 = g_node[sA.y], a2 = g_node[sA.z], a3 = g_node[sA.w];
    float4 a4 = g_node[sB.x], a5 = g_node[sB.y], a6 = g_node[sB.z], a7 = g_node[sB.w];
    float v0 = nodef[4 * dA.x + 1], v1 = nodef[4 * dA.y + 1];
    float v2 = nodef[4 * dA.z + 1], v3 = nodef[4 * dA.w + 1];
    float v4 = nodef[4 * dB.x + 1], v5 = nodef[4 * dB.y + 1];
    float v6 = nodef[4 * dB.z + 1], v7 = nodef[4 * dB.w + 1];

    #define GATE(a, v) (1.0f / (1.0f + __expf(-((a).x + (v) + be))))
    float w0 = GATE(a0, v0), w1 = GATE(a1, v1), w2 = GATE(a2, v2), w3 = GATE(a3, v3);
    float w4 = GATE(a4, v4), w5 = GATE(a5, v5), w6 = GATE(a6, v6), w7 = GATE(a7, v7);
    #undef GATE

    atomicAdd(&g_acc[dA.x], make_float4(w0 * a0.z, w0 * a0.w, 1.0f, 0.0f));
    atomicAdd(&g_acc[dA.y], make_float4(w1 * a1.z, w1 * a1.w, 1.0f, 0.0f));
    atomicAdd(&g_acc[dA.z], make_float4(w2 * a2.z, w2 * a2.w, 1.0f, 0.0f));
    atomicAdd(&g_acc[dA.w], make_float4(w3 * a3.z, w3 * a3.w, 1.0f, 0.0f));
    atomicAdd(&g_acc[dB.x], make_float4(w4 * a4.z, w4 * a4.w, 1.0f, 0.0f));
    atomicAdd(&g_acc[dB.y], make_float4(w5 * a5.z, w5 * a5.w, 1.0f, 0.0f));
    atomicAdd(&g_acc[dB.z], make_float4(w6 * a6.z, w6 * a6.w, 1.0f, 0.0f));
    atomicAdd(&g_acc[dB.w], make_float4(w7 * a7.z, w7 * a7.w, 1.0f, 0.0f));
}

// ---------------------------------------------------------------------------
// K3: out[n] = (deg>0 ? acc.xy : z) + b_out. Fully coalesced, trivial.
// ---------------------------------------------------------------------------
__global__ void out_kernel(const float* __restrict__ b_out,
                           float* __restrict__ out) {
    int n = blockIdx.x * blockDim.x + threadIdx.x;
    if (n >= N_NODES) return;
    float4 a  = g_acc[n];
    float4 nd = g_node[n];
    float s0 = (a.z > 0.f) ? a.x : nd.z;
    float s1 = (a.z > 0.f) ? a.y : nd.w;
    ((float2*)out)[n] = make_float2(s0 + b_out[0], s1 + b_out[1]);
}

// ---------------------------------------------------------------------------
extern "C" void kernel_launch(void* const* d_in, const int* in_sizes, int n_in,
                              void* d_out, int out_size) {
    const float* feat   = (const float*)d_in[0];
    const int*   src    = (const int*)  d_in[1];
    const int*   dst    = (const int*)  d_in[2];
    const float* W_in   = (const float*)d_in[3];
    const float* b_in   = (const float*)d_in[4];
    const float* W_edge = (const float*)d_in[5];
    const float* b_edge = (const float*)d_in[6];
    const float* W_out  = (const float*)d_in[7];
    const float* b_out  = (const float*)d_in[8];
    float* out = (float*)d_out;

    // async D2D copies into constant memory (graph-capturable, no allocation)
    cudaMemcpyToSymbolAsync(cW,  W_in,   HID * HID * sizeof(float), 0, cudaMemcpyDeviceToDevice, 0);
    cudaMemcpyToSymbolAsync(cB,  b_in,   HID * sizeof(float),       0, cudaMemcpyDeviceToDevice, 0);
    cudaMemcpyToSymbolAsync(cWe, W_edge, 2 * HID * sizeof(float),   0, cudaMemcpyDeviceToDevice, 0);
    cudaMemcpyToSymbolAsync(cWo, W_out,  2 * HID * sizeof(float),   0, cudaMemcpyDeviceToDevice, 0);

    input_gemm_kernel<<<(N_NODES + 127) / 128, 256>>>(feat);
    scatter_kernel<<<(N_EDGES / 8 + 255) / 256, 256>>>(src, dst, b_edge);
    out_kernel<<<(N_NODES + 255) / 256, 256>>>(b_out, out);
}

// round 15
// speedup vs baseline: 1.5771x; 1.5771x over previous
#include <cuda_runtime.h>
#include <math.h>

#define N_NODES 100000
#define N_EDGES 1600000
#define HID 64

// Scratch (no cudaMalloc allowed).
__device__ float4 g_V[HID];          // composed weights: V[k] = W_in[k,:] @ [Wu|Wv|Wo0|Wo1]
__device__ float4 g_C;               // composed bias:    c    = b_in      @ [Wu|Wv|Wo0|Wo1]
__device__ float4 g_node[N_NODES];   // (dotu, dotv, z0, z1) per node, 1.6 MB
__device__ float4 g_acc[N_NODES];    // (sum_w*z0, sum_w*z1, deg, pad), 1.6 MB

// ---------------------------------------------------------------------------
// K0: compose the weights. dotu = h·Wu = feat·(W_in@Wu) + b_in·Wu, etc.
// 16k MACs — one block, trivial.
// ---------------------------------------------------------------------------
__global__ void prep_kernel(const float* __restrict__ W_in,
                            const float* __restrict__ b_in,
                            const float* __restrict__ W_edge,
                            const float* __restrict__ W_out) {
    int k = threadIdx.x;
    if (k < HID) {
        float4 v = make_float4(0.f, 0.f, 0.f, 0.f);
#pragma unroll 8
        for (int j = 0; j < HID; j++) {
            float w = W_in[k * HID + j];
            v.x = fmaf(w, W_edge[j],            v.x);
            v.y = fmaf(w, W_edge[HID + j],      v.y);
            v.z = fmaf(w, W_out[2 * j],         v.z);
            v.w = fmaf(w, W_out[2 * j + 1],     v.w);
        }
        g_V[k] = v;
    } else if (k == HID) {
        float4 cc = make_float4(0.f, 0.f, 0.f, 0.f);
        for (int j = 0; j < HID; j++) {
            float b = b_in[j];
            cc.x = fmaf(b, W_edge[j],        cc.x);
            cc.y = fmaf(b, W_edge[HID + j],  cc.y);
            cc.z = fmaf(b, W_out[2 * j],     cc.z);
            cc.w = fmaf(b, W_out[2 * j + 1], cc.w);
        }
        g_C = cc;
    }
}

// ---------------------------------------------------------------------------
// K1: per-node functionals — g_node[n] = feat[n] @ V + c; zero g_acc[n].
// One node per quarter-warp; lane c loads feats 4c..4c+3 and 32+4c..32+4c+3
// (two float4, coalesced), 8 FMA4 each, 3-stage 8-lane shuffle reduce.
// Purely feat-bandwidth bound (25.6 MB).
// ---------------------------------------------------------------------------
__global__ void __launch_bounds__(256)
node_kernel(const float* __restrict__ feat) {
    __shared__ float4 sV[HID];
    __shared__ float4 sC;

    int tid = threadIdx.x;
    if (tid < HID) sV[tid] = g_V[tid];
    if (tid == HID) sC = g_C;
    __syncthreads();

    int lane = tid & 31;
    int warp = (blockIdx.x * blockDim.x + tid) >> 5;
    int q = lane >> 3;
    int c = lane & 7;
    int n = warp * 4 + q;
    if (n >= N_NODES) return;

    const float4* f4 = (const float4*)feat;
    float4 x0 = f4[(long long)n * 16 + c];       // feats 4c..4c+3
    float4 x1 = f4[(long long)n * 16 + 8 + c];   // feats 32+4c..32+4c+3

    float4 acc = make_float4(0.f, 0.f, 0.f, 0.f);
    const float* x0f = (const float*)&x0;
    const float* x1f = (const float*)&x1;
#pragma unroll
    for (int i = 0; i < 4; i++) {
        float xv = x0f[i];
        float4 v = sV[4 * c + i];
        acc.x = fmaf(xv, v.x, acc.x);
        acc.y = fmaf(xv, v.y, acc.y);
        acc.z = fmaf(xv, v.z, acc.z);
        acc.w = fmaf(xv, v.w, acc.w);
    }
#pragma unroll
    for (int i = 0; i < 4; i++) {
        float xv = x1f[i];
        float4 v = sV[32 + 4 * c + i];
        acc.x = fmaf(xv, v.x, acc.x);
        acc.y = fmaf(xv, v.y, acc.y);
        acc.z = fmaf(xv, v.z, acc.z);
        acc.w = fmaf(xv, v.w, acc.w);
    }
    // reduce across the 8 lanes of the quarter
#pragma unroll
    for (int off = 1; off <= 4; off <<= 1) {
        acc.x += __shfl_xor_sync(0xffffffffu, acc.x, off);
        acc.y += __shfl_xor_sync(0xffffffffu, acc.y, off);
        acc.z += __shfl_xor_sync(0xffffffffu, acc.z, off);
        acc.w += __shfl_xor_sync(0xffffffffu, acc.w, off);
    }
    if (c == 0) {
        float4 cc = sC;
        g_node[n] = make_float4(acc.x + cc.x, acc.y + cc.y,
                                acc.z + cc.z, acc.w + cc.w);
        g_acc[n] = make_float4(0.f, 0.f, 0.f, 0.f);
    }
}

// ---------------------------------------------------------------------------
// K2: edge scatter — gate + projected message, ONE vector RED per edge:
//   g_acc[dst] += (w*z0, w*z1, 1, 0).  8 edges per thread (MLP 16).
// ---------------------------------------------------------------------------
__global__ void scatter_kernel(const int* __restrict__ src,
                               const int* __restrict__ dst,
                               const float* __restrict__ b_edge) {
    int t = blockIdx.x * blockDim.x + threadIdx.x;
    if (t * 8 >= N_EDGES) return;
    const int4* s4 = (const int4*)src;
    const int4* d4 = (const int4*)dst;
    int4 sA = s4[2 * t], sB = s4[2 * t + 1];
    int4 dA = d4[2 * t], dB = d4[2 * t + 1];
    float be = b_edge[0];
    const float* nodef = (const float*)g_node;

    // issue all random loads first (MLP 16)
    float4 a0 = g_node[sA.x], a1 = g_node[sA.y], a2 = g_node[sA.z], a3 = g_node[sA.w];
    float4 a4 = g_node[sB.x], a5 = g_node[sB.y], a6 = g_node[sB.z], a7 = g_node[sB.w];
    float v0 = nodef[4 * dA.x + 1], v1 = nodef[4 * dA.y + 1];
    float v2 = nodef[4 * dA.z + 1], v3 = nodef[4 * dA.w + 1];
    float v4 = nodef[4 * dB.x + 1], v5 = nodef[4 * dB.y + 1];
    float v6 = nodef[4 * dB.z + 1], v7 = nodef[4 * dB.w + 1];

    #define GATE(a, v) (1.0f / (1.0f + __expf(-((a).x + (v) + be))))
    float w0 = GATE(a0, v0), w1 = GATE(a1, v1), w2 = GATE(a2, v2), w3 = GATE(a3, v3);
    float w4 = GATE(a4, v4), w5 = GATE(a5, v5), w6 = GATE(a6, v6), w7 = GATE(a7, v7);
    #undef GATE

    atomicAdd(&g_acc[dA.x], make_float4(w0 * a0.z, w0 * a0.w, 1.0f, 0.0f));
    atomicAdd(&g_acc[dA.y], make_float4(w1 * a1.z, w1 * a1.w, 1.0f, 0.0f));
    atomicAdd(&g_acc[dA.z], make_float4(w2 * a2.z, w2 * a2.w, 1.0f, 0.0f));
    atomicAdd(&g_acc[dA.w], make_float4(w3 * a3.z, w3 * a3.w, 1.0f, 0.0f));
    atomicAdd(&g_acc[dB.x], make_float4(w4 * a4.z, w4 * a4.w, 1.0f, 0.0f));
    atomicAdd(&g_acc[dB.y], make_float4(w5 * a5.z, w5 * a5.w, 1.0f, 0.0f));
    atomicAdd(&g_acc[dB.z], make_float4(w6 * a6.z, w6 * a6.w, 1.0f, 0.0f));
    atomicAdd(&g_acc[dB.w], make_float4(w7 * a7.z, w7 * a7.w, 1.0f, 0.0f));
}

// ---------------------------------------------------------------------------
// K3: out[n] = (deg>0 ? acc.xy : z) + b_out. Fully coalesced, trivial.
// ---------------------------------------------------------------------------
__global__ void out_kernel(const float* __restrict__ b_out,
                           float* __restrict__ out) {
    int n = blockIdx.x * blockDim.x + threadIdx.x;
    if (n >= N_NODES) return;
    float4 a  = g_acc[n];
    float4 nd = g_node[n];
    float s0 = (a.z > 0.f) ? a.x : nd.z;
    float s1 = (a.z > 0.f) ? a.y : nd.w;
    ((float2*)out)[n] = make_float2(s0 + b_out[0], s1 + b_out[1]);
}

// ---------------------------------------------------------------------------
extern "C" void kernel_launch(void* const* d_in, const int* in_sizes, int n_in,
                              void* d_out, int out_size) {
    const float* feat   = (const float*)d_in[0];
    const int*   src    = (const int*)  d_in[1];
    const int*   dst    = (const int*)  d_in[2];
    const float* W_in   = (const float*)d_in[3];
    const float* b_in   = (const float*)d_in[4];
    const float* W_edge = (const float*)d_in[5];
    const float* b_edge = (const float*)d_in[6];
    const float* W_out  = (const float*)d_in[7];
    const float* b_out  = (const float*)d_in[8];
    float* out = (float*)d_out;

    prep_kernel<<<1, 128>>>(W_in, b_in, W_edge, W_out);
    // 32 nodes per 256-thread block -> 3125 blocks exactly
    node_kernel<<<N_NODES / 32, 256>>>(feat);
    scatter_kernel<<<(N_EDGES / 8 + 255) / 256, 256>>>(src, dst, b_edge);
    out_kernel<<<(N_NODES + 255) / 256, 256>>>(b_out, out);
}

// round 16
// speedup vs baseline: 1.5856x; 1.0053x over previous
#include <cuda_runtime.h>
#include <math.h>

#define N_NODES 100000
#define N_EDGES 1600000
#define HID 64

// Scratch (no cudaMalloc allowed).
__device__ float4 g_V[HID];          // composed weights: V[k] = W_in[k,:] @ [Wu|Wv|Wo0|Wo1]
__device__ float4 g_C;               // composed bias:    c    = b_in      @ [Wu|Wv|Wo0|Wo1]
__device__ float4 g_node[N_NODES];   // (.5*dotu, .5*(dotv+be), .5*z0, .5*z1), 1.6 MB
__device__ float4 g_acc[N_NODES];    // (sum_w*z0, sum_w*z1, deg, pad), 1.6 MB

__device__ __forceinline__ float fast_tanh(float x) {
    float t;
    asm("tanh.approx.f32 %0, %1;" : "=f"(t) : "f"(x));
    return t;
}

// ---------------------------------------------------------------------------
// K0: compose the weights. dotu = h·Wu = feat·(W_in@Wu) + b_in·Wu, etc.
// ---------------------------------------------------------------------------
__global__ void prep_kernel(const float* __restrict__ W_in,
                            const float* __restrict__ b_in,
                            const float* __restrict__ W_edge,
                            const float* __restrict__ W_out) {
    int k = threadIdx.x;
    if (k < HID) {
        float4 v = make_float4(0.f, 0.f, 0.f, 0.f);
#pragma unroll 8
        for (int j = 0; j < HID; j++) {
            float w = W_in[k * HID + j];
            v.x = fmaf(w, W_edge[j],        v.x);
            v.y = fmaf(w, W_edge[HID + j],  v.y);
            v.z = fmaf(w, W_out[2 * j],     v.z);
            v.w = fmaf(w, W_out[2 * j + 1], v.w);
        }
        g_V[k] = v;
    } else if (k == HID) {
        float4 cc = make_float4(0.f, 0.f, 0.f, 0.f);
        for (int j = 0; j < HID; j++) {
            float b = b_in[j];
            cc.x = fmaf(b, W_edge[j],        cc.x);
            cc.y = fmaf(b, W_edge[HID + j],  cc.y);
            cc.z = fmaf(b, W_out[2 * j],     cc.z);
            cc.w = fmaf(b, W_out[2 * j + 1], cc.w);
        }
        g_C = cc;
    }
}

// ---------------------------------------------------------------------------
// K1: per-node functionals, pre-scaled for the tanh gate:
//   g_node[n] = ( .5*dotu, .5*(dotv+b_edge), .5*z0, .5*z1 );  g_acc[n] = 0.
// One node per quarter-warp; feat-bandwidth bound (25.6 MB).
// ---------------------------------------------------------------------------
__global__ void __launch_bounds__(256)
node_kernel(const float* __restrict__ feat, const float* __restrict__ b_edge) {
    __shared__ float4 sV[HID];
    __shared__ float4 sC;

    int tid = threadIdx.x;
    if (tid < HID) sV[tid] = g_V[tid];
    if (tid == HID) sC = g_C;
    __syncthreads();

    int lane = tid & 31;
    int warp = (blockIdx.x * blockDim.x + tid) >> 5;
    int q = lane >> 3;
    int c = lane & 7;
    int n = warp * 4 + q;
    if (n >= N_NODES) return;

    const float4* f4 = (const float4*)feat;
    float4 x0 = f4[(long long)n * 16 + c];
    float4 x1 = f4[(long long)n * 16 + 8 + c];

    float4 acc = make_float4(0.f, 0.f, 0.f, 0.f);
    const float* x0f = (const float*)&x0;
    const float* x1f = (const float*)&x1;
#pragma unroll
    for (int i = 0; i < 4; i++) {
        float xv = x0f[i];
        float4 v = sV[4 * c + i];
        acc.x = fmaf(xv, v.x, acc.x);
        acc.y = fmaf(xv, v.y, acc.y);
        acc.z = fmaf(xv, v.z, acc.z);
        acc.w = fmaf(xv, v.w, acc.w);
    }
#pragma unroll
    for (int i = 0; i < 4; i++) {
        float xv = x1f[i];
        float4 v = sV[32 + 4 * c + i];
        acc.x = fmaf(xv, v.x, acc.x);
        acc.y = fmaf(xv, v.y, acc.y);
        acc.z = fmaf(xv, v.z, acc.z);
        acc.w = fmaf(xv, v.w, acc.w);
    }
#pragma unroll
    for (int off = 1; off <= 4; off <<= 1) {
        acc.x += __shfl_xor_sync(0xffffffffu, acc.x, off);
        acc.y += __shfl_xor_sync(0xffffffffu, acc.y, off);
        acc.z += __shfl_xor_sync(0xffffffffu, acc.z, off);
        acc.w += __shfl_xor_sync(0xffffffffu, acc.w, off);
    }
    if (c == 0) {
        float4 cc = sC;
        float be = b_edge[0];
        g_node[n] = make_float4(0.5f * (acc.x + cc.x),
                                0.5f * (acc.y + cc.y + be),
                                0.5f * (acc.z + cc.z),
                                0.5f * (acc.w + cc.w));
        g_acc[n] = make_float4(0.f, 0.f, 0.f, 0.f);
    }
}

// ---------------------------------------------------------------------------
// K2: edge scatter. Per edge: t = tanh(hdu[s] + hdv[d]);
//   msg = (fma(hz0,t,hz0), fma(hz1,t,hz1));  g_acc[d] += (msg, 1, 0).
// ONE MUFU per edge (was two). 8 edges per thread (MLP 16).
// ---------------------------------------------------------------------------
__global__ void scatter_kernel(const int* __restrict__ src,
                               const int* __restrict__ dst) {
    int t = blockIdx.x * blockDim.x + threadIdx.x;
    if (t * 8 >= N_EDGES) return;
    const int4* s4 = (const int4*)src;
    const int4* d4 = (const int4*)dst;
    int4 sA = s4[2 * t], sB = s4[2 * t + 1];
    int4 dA = d4[2 * t], dB = d4[2 * t + 1];
    const float* nodef = (const float*)g_node;

    // issue all random loads first (MLP 16)
    float4 a0 = g_node[sA.x], a1 = g_node[sA.y], a2 = g_node[sA.z], a3 = g_node[sA.w];
    float4 a4 = g_node[sB.x], a5 = g_node[sB.y], a6 = g_node[sB.z], a7 = g_node[sB.w];
    float v0 = nodef[4 * dA.x + 1], v1 = nodef[4 * dA.y + 1];
    float v2 = nodef[4 * dA.z + 1], v3 = nodef[4 * dA.w + 1];
    float v4 = nodef[4 * dB.x + 1], v5 = nodef[4 * dB.y + 1];
    float v6 = nodef[4 * dB.z + 1], v7 = nodef[4 * dB.w + 1];

    float t0 = fast_tanh(a0.x + v0), t1 = fast_tanh(a1.x + v1);
    float t2 = fast_tanh(a2.x + v2), t3 = fast_tanh(a3.x + v3);
    float t4 = fast_tanh(a4.x + v4), t5 = fast_tanh(a5.x + v5);
    float t6 = fast_tanh(a6.x + v6), t7 = fast_tanh(a7.x + v7);

    atomicAdd(&g_acc[dA.x], make_float4(fmaf(a0.z, t0, a0.z), fmaf(a0.w, t0, a0.w), 1.0f, 0.0f));
    atomicAdd(&g_acc[dA.y], make_float4(fmaf(a1.z, t1, a1.z), fmaf(a1.w, t1, a1.w), 1.0f, 0.0f));
    atomicAdd(&g_acc[dA.z], make_float4(fmaf(a2.z, t2, a2.z), fmaf(a2.w, t2, a2.w), 1.0f, 0.0f));
    atomicAdd(&g_acc[dA.w], make_float4(fmaf(a3.z, t3, a3.z), fmaf(a3.w, t3, a3.w), 1.0f, 0.0f));
    atomicAdd(&g_acc[dB.x], make_float4(fmaf(a4.z, t4, a4.z), fmaf(a4.w, t4, a4.w), 1.0f, 0.0f));
    atomicAdd(&g_acc[dB.y], make_float4(fmaf(a5.z, t5, a5.z), fmaf(a5.w, t5, a5.w), 1.0f, 0.0f));
    atomicAdd(&g_acc[dB.z], make_float4(fmaf(a6.z, t6, a6.z), fmaf(a6.w, t6, a6.w), 1.0f, 0.0f));
    atomicAdd(&g_acc[dB.w], make_float4(fmaf(a7.z, t7, a7.z), fmaf(a7.w, t7, a7.w), 1.0f, 0.0f));
}

// ---------------------------------------------------------------------------
// K3: out[n] = (deg>0 ? acc.xy : 2*hz) + b_out. Coalesced, trivial.
// ---------------------------------------------------------------------------
__global__ void out_kernel(const float* __restrict__ b_out,
                           float* __restrict__ out) {
    int n = blockIdx.x * blockDim.x + threadIdx.x;
    if (n >= N_NODES) return;
    float4 a  = g_acc[n];
    float4 nd = g_node[n];
    float s0 = (a.z > 0.f) ? a.x : 2.0f * nd.z;
    float s1 = (a.z > 0.f) ? a.y : 2.0f * nd.w;
    ((float2*)out)[n] = make_float2(s0 + b_out[0], s1 + b_out[1]);
}

// ---------------------------------------------------------------------------
extern "C" void kernel_launch(void* const* d_in, const int* in_sizes, int n_in,
                              void* d_out, int out_size) {
    const float* feat   = (const float*)d_in[0];
    const int*   src    = (const int*)  d_in[1];
    const int*   dst    = (const int*)  d_in[2];
    const float* W_in   = (const float*)d_in[3];
    const float* b_in   = (const float*)d_in[4];
    const float* W_edge = (const float*)d_in[5];
    const float* b_edge = (const float*)d_in[6];
    const float* W_out  = (const float*)d_in[7];
    const float* b_out  = (const float*)d_in[8];
    float* out = (float*)d_out;

    prep_kernel<<<1, 128>>>(W_in, b_in, W_edge, W_out);
    node_kernel<<<N_NODES / 32, 256>>>(feat, b_edge);
    scatter_kernel<<<(N_EDGES / 8 + 255) / 256, 256>>>(src, dst);
    out_kernel<<<(N_NODES + 255) / 256, 256>>>(b_out, out);
}

// round 17
// speedup vs baseline: 1.5866x; 1.0007x over previous
#include <cuda_runtime.h>
#include <math.h>

#define N_NODES 100000
#define N_EDGES 1600000
#define HID 64

// Scratch (no cudaMalloc allowed).
__device__ float4 g_V[HID];           // composed weights: V[k] = W_in[k,:] @ [Wu|Wv|Wo0|Wo1]
__device__ float4 g_C;                // composed bias
__device__ float4 g_node[N_NODES];    // (.5*dotu, .5*(dotv+be), .5*z0, .5*z1), 1.6 MB
__device__ float2 g_acc[N_NODES];     // (sum w*z0, sum w*z1), 0.8 MB; (0,0) <=> deg==0

__device__ __forceinline__ float fast_tanh(float x) {
    float t;
    asm("tanh.approx.f32 %0, %1;" : "=f"(t) : "f"(x));
    return t;
}

// ---------------------------------------------------------------------------
// K0: compose the weights. dotu = h·Wu = feat·(W_in@Wu) + b_in·Wu, etc.
// ---------------------------------------------------------------------------
__global__ void prep_kernel(const float* __restrict__ W_in,
                            const float* __restrict__ b_in,
                            const float* __restrict__ W_edge,
                            const float* __restrict__ W_out) {
    int k = threadIdx.x;
    if (k < HID) {
        float4 v = make_float4(0.f, 0.f, 0.f, 0.f);
#pragma unroll 8
        for (int j = 0; j < HID; j++) {
            float w = W_in[k * HID + j];
            v.x = fmaf(w, W_edge[j],        v.x);
            v.y = fmaf(w, W_edge[HID + j],  v.y);
            v.z = fmaf(w, W_out[2 * j],     v.z);
            v.w = fmaf(w, W_out[2 * j + 1], v.w);
        }
        g_V[k] = v;
    } else if (k == HID) {
        float4 cc = make_float4(0.f, 0.f, 0.f, 0.f);
        for (int j = 0; j < HID; j++) {
            float b = b_in[j];
            cc.x = fmaf(b, W_edge[j],        cc.x);
            cc.y = fmaf(b, W_edge[HID + j],  cc.y);
            cc.z = fmaf(b, W_out[2 * j],     cc.z);
            cc.w = fmaf(b, W_out[2 * j + 1], cc.w);
        }
        g_C = cc;
    }
}

// ---------------------------------------------------------------------------
// K1: per-node functionals, pre-scaled for the tanh gate:
//   g_node[n] = ( .5*dotu, .5*(dotv+b_edge), .5*z0, .5*z1 );  g_acc[n] = 0.
// One node per quarter-warp; feat-bandwidth bound (25.6 MB).
// ---------------------------------------------------------------------------
__global__ void __launch_bounds__(256)
node_kernel(const float* __restrict__ feat, const float* __restrict__ b_edge) {
    __shared__ float4 sV[HID];
    __shared__ float4 sC;

    int tid = threadIdx.x;
    if (tid < HID) sV[tid] = g_V[tid];
    if (tid == HID) sC = g_C;
    __syncthreads();

    int lane = tid & 31;
    int warp = (blockIdx.x * blockDim.x + tid) >> 5;
    int q = lane >> 3;
    int c = lane & 7;
    int n = warp * 4 + q;
    if (n >= N_NODES) return;

    const float4* f4 = (const float4*)feat;
    float4 x0 = f4[(long long)n * 16 + c];
    float4 x1 = f4[(long long)n * 16 + 8 + c];

    float4 acc = make_float4(0.f, 0.f, 0.f, 0.f);
    const float* x0f = (const float*)&x0;
    const float* x1f = (const float*)&x1;
#pragma unroll
    for (int i = 0; i < 4; i++) {
        float xv = x0f[i];
        float4 v = sV[4 * c + i];
        acc.x = fmaf(xv, v.x, acc.x);
        acc.y = fmaf(xv, v.y, acc.y);
        acc.z = fmaf(xv, v.z, acc.z);
        acc.w = fmaf(xv, v.w, acc.w);
    }
#pragma unroll
    for (int i = 0; i < 4; i++) {
        float xv = x1f[i];
        float4 v = sV[32 + 4 * c + i];
        acc.x = fmaf(xv, v.x, acc.x);
        acc.y = fmaf(xv, v.y, acc.y);
        acc.z = fmaf(xv, v.z, acc.z);
        acc.w = fmaf(xv, v.w, acc.w);
    }
#pragma unroll
    for (int off = 1; off <= 4; off <<= 1) {
        acc.x += __shfl_xor_sync(0xffffffffu, acc.x, off);
        acc.y += __shfl_xor_sync(0xffffffffu, acc.y, off);
        acc.z += __shfl_xor_sync(0xffffffffu, acc.z, off);
        acc.w += __shfl_xor_sync(0xffffffffu, acc.w, off);
    }
    if (c == 0) {
        float4 cc = sC;
        float be = b_edge[0];
        g_node[n] = make_float4(0.5f * (acc.x + cc.x),
                                0.5f * (acc.y + cc.y + be),
                                0.5f * (acc.z + cc.z),
                                0.5f * (acc.w + cc.w));
        g_acc[n] = make_float2(0.f, 0.f);
    }
}

// ---------------------------------------------------------------------------
// K2: edge scatter. Per edge: t = tanh(hdu[s] + hdv[d]);
//   g_acc[d] += (fma(hz0,t,hz0), fma(hz1,t,hz1))   -- ONE 8-byte vector RED.
// 8 edges per thread (MLP 16).
// ---------------------------------------------------------------------------
__global__ void scatter_kernel(const int* __restrict__ src,
                               const int* __restrict__ dst) {
    int t = blockIdx.x * blockDim.x + threadIdx.x;
    if (t * 8 >= N_EDGES) return;
    const int4* s4 = (const int4*)src;
    const int4* d4 = (const int4*)dst;
    int4 sA = s4[2 * t], sB = s4[2 * t + 1];
    int4 dA = d4[2 * t], dB = d4[2 * t + 1];
    const float* nodef = (const float*)g_node;

    // issue all random loads first (MLP 16)
    float4 a0 = g_node[sA.x], a1 = g_node[sA.y], a2 = g_node[sA.z], a3 = g_node[sA.w];
    float4 a4 = g_node[sB.x], a5 = g_node[sB.y], a6 = g_node[sB.z], a7 = g_node[sB.w];
    float v0 = nodef[4 * dA.x + 1], v1 = nodef[4 * dA.y + 1];
    float v2 = nodef[4 * dA.z + 1], v3 = nodef[4 * dA.w + 1];
    float v4 = nodef[4 * dB.x + 1], v5 = nodef[4 * dB.y + 1];
    float v6 = nodef[4 * dB.z + 1], v7 = nodef[4 * dB.w + 1];

    float t0 = fast_tanh(a0.x + v0), t1 = fast_tanh(a1.x + v1);
    float t2 = fast_tanh(a2.x + v2), t3 = fast_tanh(a3.x + v3);
    float t4 = fast_tanh(a4.x + v4), t5 = fast_tanh(a5.x + v5);
    float t6 = fast_tanh(a6.x + v6), t7 = fast_tanh(a7.x + v7);

    atomicAdd(&g_acc[dA.x], make_float2(fmaf(a0.z, t0, a0.z), fmaf(a0.w, t0, a0.w)));
    atomicAdd(&g_acc[dA.y], make_float2(fmaf(a1.z, t1, a1.z), fmaf(a1.w, t1, a1.w)));
    atomicAdd(&g_acc[dA.z], make_float2(fmaf(a2.z, t2, a2.z), fmaf(a2.w, t2, a2.w)));
    atomicAdd(&g_acc[dA.w], make_float2(fmaf(a3.z, t3, a3.z), fmaf(a3.w, t3, a3.w)));
    atomicAdd(&g_acc[dB.x], make_float2(fmaf(a4.z, t4, a4.z), fmaf(a4.w, t4, a4.w)));
    atomicAdd(&g_acc[dB.y], make_float2(fmaf(a5.z, t5, a5.z), fmaf(a5.w, t5, a5.w)));
    atomicAdd(&g_acc[dB.z], make_float2(fmaf(a6.z, t6, a6.z), fmaf(a6.w, t6, a6.w)));
    atomicAdd(&g_acc[dB.w], make_float2(fmaf(a7.z, t7, a7.z), fmaf(a7.w, t7, a7.w)));
}

// ---------------------------------------------------------------------------
// K3: out[n] = (acc != 0 ? acc : 2*hz) + b_out. Two nodes per thread.
// acc == (0,0) exactly <=> deg==0 (w strictly in (0,1); joint exact
// cancellation over the fixed dataset has probability ~2^-50 per node).
// ---------------------------------------------------------------------------
__global__ void out_kernel(const float* __restrict__ b_out,
                           float* __restrict__ out) {
    int i = blockIdx.x * blockDim.x + threadIdx.x;   // pair index
    if (i * 2 >= N_NODES) return;
    int n0 = 2 * i, n1 = 2 * i + 1;

    float4 a01 = ((const float4*)g_acc)[i];          // acc[n0], acc[n1]
    float2 z0 = *(const float2*)&(((const float*)g_node)[4 * n0 + 2]);
    float2 z1 = *(const float2*)&(((const float*)g_node)[4 * n1 + 2]);
    float b0 = b_out[0], b1 = b_out[1];

    bool e0 = (a01.x != 0.f) || (a01.y != 0.f);
    bool e1 = (a01.z != 0.f) || (a01.w != 0.f);
    float4 r;
    r.x = (e0 ? a01.x : 2.0f * z0.x) + b0;
    r.y = (e0 ? a01.y : 2.0f * z0.y) + b1;
    r.z = (e1 ? a01.z : 2.0f * z1.x) + b0;
    r.w = (e1 ? a01.w : 2.0f * z1.y) + b1;
    ((float4*)out)[i] = r;
}

// ---------------------------------------------------------------------------
extern "C" void kernel_launch(void* const* d_in, const int* in_sizes, int n_in,
                              void* d_out, int out_size) {
    const float* feat   = (const float*)d_in[0];
    const int*   src    = (const int*)  d_in[1];
    const int*   dst    = (const int*)  d_in[2];
    const float* W_in   = (const float*)d_in[3];
    const float* b_in   = (const float*)d_in[4];
    const float* W_edge = (const float*)d_in[5];
    const float* b_edge = (const float*)d_in[6];
    const float* W_out  = (const float*)d_in[7];
    const float* b_out  = (const float*)d_in[8];
    float* out = (float*)d_out;

    prep_kernel<<<1, 128>>>(W_in, b_in, W_edge, W_out);
    node_kernel<<<N_NODES / 32, 256>>>(feat, b_edge);
    scatter_kernel<<<(N_EDGES / 8 + 255) / 256, 256>>>(src, dst);
    out_kernel<<<(N_NODES / 2 + 255) / 256, 256>>>(b_out, out);
}